// round 15
// baseline (speedup 1.0000x reference)
#include <cuda_runtime.h>

#define NOBJ  2048
#define NHD   8
#define NP    32
#define HD    32
#define EMBED 256
#define FFNW  1024
#define NUM_IMG 4
#define IMH   160
#define IMW   160
#define HW    25600     // 160*160
#define LN_EPS 1e-5f

// ---------------- scratch (device globals; no runtime alloc) ----------------
__device__ float g_keyT[(size_t)NUM_IMG * NHD * HW * HD];   // (img,h,pix,d) 100MB
__device__ float g_valT[(size_t)NUM_IMG * NHD * HW * HD];   // 100MB
__device__ float g_offsets[(size_t)NOBJ * NHD * NP * 2];
__device__ float g_attn[(size_t)NOBJ * EMBED];
__device__ float g_x1[(size_t)NOBJ * EMBED];
__device__ float g_ffn[(size_t)NOBJ * FFNW];
__device__ float g_part[(size_t)4 * NOBJ * EMBED];          // split-K partials (8MB)

// ---------------- transpose key/value: (img, c=h*32+d, y, x) -> (img,h, yx, d)
__global__ void transpose_kernel(const float* __restrict__ key_feat,
                                 const float* __restrict__ value) {
    __shared__ float sh[32][33];
    const float* in  = blockIdx.z ? value  : key_feat;
    float*       out = blockIdx.z ? g_valT : g_keyT;
    int ih  = blockIdx.y;              // img*8 + h
    int img = ih >> 3, h = ih & 7;
    int pix0 = blockIdx.x * 32;
    int t = threadIdx.x;
    size_t cbase = ((size_t)img * EMBED + h * HD) * HW;
#pragma unroll
    for (int pass = 0; pass < 4; pass++) {
        int c   = pass * 8 + (t >> 5);
        int pix = t & 31;
        sh[c][pix] = in[cbase + (size_t)c * HW + pix0 + pix];
    }
    __syncthreads();
    size_t obase = ((size_t)ih * HW + pix0) * HD;
#pragma unroll
    for (int pass = 0; pass < 4; pass++) {
        int pix = pass * 8 + (t >> 5);
        int c   = t & 31;
        out[obase + (size_t)pix * HD + c] = sh[c][pix];
    }
}

// ---------------- fp32 tiled GEMM, register double-buffered ----------------
// Tile 64x64, BK=16, 256 threads, 4x4 per thread.
// mode 0: C = A@B + bias
// mode 2: C = relu(A@B + bias)
// mode 3: split-K partial: g-part style, C + bz*M*N = A@B(chunk), raw
__global__ void gemm64(const float* __restrict__ A, const float* __restrict__ B,
                       const float* __restrict__ bias,
                       float* __restrict__ C, int M, int N, int K, int mode) {
    __shared__ float As[16][64];
    __shared__ float Bs[16][64];
    const int bm = blockIdx.y * 64, bn = blockIdx.x * 64;
    const int tid = threadIdx.x;
    const int tx = tid & 15, ty = tid >> 4;

    const int Kc    = K / gridDim.z;          // K-chunk for this block
    const int kbase = blockIdx.z * Kc;
    const int nk    = Kc >> 4;

    float acc[4][4];
#pragma unroll
    for (int i = 0; i < 4; i++)
#pragma unroll
        for (int j = 0; j < 4; j++) acc[i][j] = 0.f;

    const int arow = tid >> 2, aq = tid & 3;   // A: 64 rows x 4 float4
    const int brow = tid >> 4, bq = tid & 15;  // B: 16 rows x 16 float4

    const float* Aptr = A + (size_t)(bm + arow) * K + kbase + aq * 4;
    const float* Bptr = B + (size_t)(kbase + brow) * N + bn + bq * 4;

    // preload tile 0
    float4 a4 = *(const float4*)Aptr;
    float4 b4 = *(const float4*)Bptr;

    for (int kt = 0; kt < nk; kt++) {
        // store current tile to smem
        As[aq * 4 + 0][arow] = a4.x;
        As[aq * 4 + 1][arow] = a4.y;
        As[aq * 4 + 2][arow] = a4.z;
        As[aq * 4 + 3][arow] = a4.w;
        *(float4*)&Bs[brow][bq * 4] = b4;
        __syncthreads();

        // prefetch next tile while computing this one
        if (kt + 1 < nk) {
            a4 = *(const float4*)(Aptr + (kt + 1) * 16);
            b4 = *(const float4*)(Bptr + (size_t)(kt + 1) * 16 * N);
        }

#pragma unroll
        for (int kk = 0; kk < 16; kk++) {
            float4 av = *(const float4*)&As[kk][ty * 4];
            float4 bv = *(const float4*)&Bs[kk][tx * 4];
            float a[4] = {av.x, av.y, av.z, av.w};
            float b[4] = {bv.x, bv.y, bv.z, bv.w};
#pragma unroll
            for (int m = 0; m < 4; m++)
#pragma unroll
                for (int n = 0; n < 4; n++) acc[m][n] += a[m] * b[n];
        }
        __syncthreads();
    }

    float* Cb = (mode == 3) ? (C + (size_t)blockIdx.z * M * N) : C;
#pragma unroll
    for (int m = 0; m < 4; m++) {
        int r = bm + ty * 4 + m;
#pragma unroll
        for (int n = 0; n < 4; n++) {
            int c = bn + tx * 4 + n;
            float v = acc[m][n];
            if (mode != 3) v += bias[c];
            if (mode == 2) v = fmaxf(v, 0.f);
            Cb[(size_t)r * N + c] = v;
        }
    }
}

// ------- fused split-K reduce + bias + residual + layernorm (256 cols) ------
__device__ __forceinline__ float block_sum256(float v, float* red) {
#pragma unroll
    for (int o = 16; o; o >>= 1) v += __shfl_xor_sync(0xffffffffu, v, o);
    int warp = threadIdx.x >> 5;
    if ((threadIdx.x & 31) == 0) red[warp] = v;
    __syncthreads();
    float s = red[0] + red[1] + red[2] + red[3] + red[4] + red[5] + red[6] + red[7];
    __syncthreads();
    return s;
}

__global__ void reduce_ln_kernel(const float* __restrict__ part, int nsplit,
                                 const float* __restrict__ bias,
                                 const float* __restrict__ res,
                                 const float* __restrict__ g,
                                 const float* __restrict__ b,
                                 float* __restrict__ out) {
    __shared__ float red[8];
    int row = blockIdx.x, t = threadIdx.x;
    size_t off = (size_t)row * EMBED + t;
    float v = bias[t] + res[off];
#pragma unroll 4
    for (int s = 0; s < nsplit; s++)
        v += part[(size_t)s * NOBJ * EMBED + off];
    float mean = block_sum256(v, red) * (1.f / EMBED);
    float d = v - mean;
    float var = block_sum256(d * d, red) * (1.f / EMBED);
    out[off] = d * rsqrtf(var + LN_EPS) * g[t] + b[t];
}

// ---------------- sampling + attention: one block per (n, h) ----------------
__global__ void sample_kernel(const float* __restrict__ query,
                              const float* __restrict__ x2d,
                              const float* __restrict__ maskin,
                              const float* __restrict__ xy,
                              const float* __restrict__ strides,
                              const int*   __restrict__ imgind,
                              float* __restrict__ out_v, float* __restrict__ out_a,
                              float* __restrict__ out_m, float* __restrict__ out_x2d,
                              float* __restrict__ attn_out) {
    const int nh = blockIdx.x;
    const int n = nh >> 3, h = nh & 7;
    const int tid = threadIdx.x;
    const int p = tid >> 3, dg = tid & 7;

    __shared__ float s_v[NP][HD + 1];
    __shared__ float s_a[NP], s_asm[NP], s_mask[NP], s_x2d[2][NP];

    float st = strides[n];
    float ox = g_offsets[(size_t)n * 512 + (h * NP + p) * 2 + 0];
    float oy = g_offsets[(size_t)n * 512 + (h * NP + p) * 2 + 1];
    float lx = xy[n * 2 + 0] + ox * st;
    float ly = xy[n * 2 + 1] + oy * st;
    float gx = lx * (2.0f / (IMW * 4.0f)) - 1.0f;
    float gy = ly * (2.0f / (IMH * 4.0f)) - 1.0f;
    float ixf = ((gx + 1.0f) * IMW - 1.0f) * 0.5f;
    float iyf = ((gy + 1.0f) * IMH - 1.0f) * 0.5f;
    float x0f = floorf(ixf), y0f = floorf(iyf);
    float wx = ixf - x0f, wy = iyf - y0f;
    int x0 = (int)x0f, y0 = (int)y0f;
    int x1 = x0 + 1, y1 = y0 + 1;
    int x0c = min(max(x0, 0), IMW - 1), x1c = min(max(x1, 0), IMW - 1);
    int y0c = min(max(y0, 0), IMH - 1), y1c = min(max(y1, 0), IMH - 1);
    float w00 = (1.f - wx) * (1.f - wy), w10 = wx * (1.f - wy);
    float w01 = (1.f - wx) * wy,         w11 = wx * wy;

    int imi = imgind[n];
    size_t fb = ((size_t)(imi * NHD + h)) * HW;
    const float* kb = g_keyT + fb * HD;
    const float* vb = g_valT + fb * HD;
    size_t o00 = ((size_t)(y0c * IMW + x0c)) * HD + dg * 4;
    size_t o10 = ((size_t)(y0c * IMW + x1c)) * HD + dg * 4;
    size_t o01 = ((size_t)(y1c * IMW + x0c)) * HD + dg * 4;
    size_t o11 = ((size_t)(y1c * IMW + x1c)) * HD + dg * 4;

    float4 k00 = *(const float4*)(kb + o00);
    float4 k10 = *(const float4*)(kb + o10);
    float4 k01 = *(const float4*)(kb + o01);
    float4 k11 = *(const float4*)(kb + o11);
    float kv0 = w00 * k00.x + w10 * k10.x + w01 * k01.x + w11 * k11.x;
    float kv1 = w00 * k00.y + w10 * k10.y + w01 * k01.y + w11 * k11.y;
    float kv2 = w00 * k00.z + w10 * k10.z + w01 * k01.z + w11 * k11.z;
    float kv3 = w00 * k00.w + w10 * k10.w + w01 * k01.w + w11 * k11.w;

    float4 q4 = *(const float4*)(query + (size_t)nh * HD + dg * 4);
    float part = q4.x * kv0 + q4.y * kv1 + q4.z * kv2 + q4.w * kv3;

    float4 v00 = *(const float4*)(vb + o00);
    float4 v10 = *(const float4*)(vb + o10);
    float4 v01 = *(const float4*)(vb + o01);
    float4 v11 = *(const float4*)(vb + o11);
    s_v[p][dg * 4 + 0] = w00 * v00.x + w10 * v10.x + w01 * v01.x + w11 * v11.x;
    s_v[p][dg * 4 + 1] = w00 * v00.y + w10 * v10.y + w01 * v01.y + w11 * v11.y;
    s_v[p][dg * 4 + 2] = w00 * v00.z + w10 * v10.z + w01 * v01.z + w11 * v11.z;
    s_v[p][dg * 4 + 3] = w00 * v00.w + w10 * v10.w + w01 * v01.w + w11 * v11.w;

    part += __shfl_xor_sync(0xffffffffu, part, 1);
    part += __shfl_xor_sync(0xffffffffu, part, 2);
    part += __shfl_xor_sync(0xffffffffu, part, 4);

    if (dg == 0) {
        s_a[p] = part * 0.17677669529663687f;   // 1/sqrt(HD)
        const float* mb = maskin + (size_t)imi * HW;
        float m = 0.f;
        if (x0 >= 0 && x0 < IMW && y0 >= 0 && y0 < IMH) m += w00 * mb[y0c * IMW + x0c];
        if (x1 >= 0 && x1 < IMW && y0 >= 0 && y0 < IMH) m += w10 * mb[y0c * IMW + x1c];
        if (x0 >= 0 && x0 < IMW && y1 >= 0 && y1 < IMH) m += w01 * mb[y1c * IMW + x0c];
        if (x1 >= 0 && x1 < IMW && y1 >= 0 && y1 < IMH) m += w11 * mb[y1c * IMW + x1c];
        s_mask[p] = m;
        const float* xb0 = x2d + (size_t)imi * 2 * HW;
        const float* xb1 = xb0 + HW;
        s_x2d[0][p] = w00 * xb0[y0c * IMW + x0c] + w10 * xb0[y0c * IMW + x1c]
                    + w01 * xb0[y1c * IMW + x0c] + w11 * xb0[y1c * IMW + x1c];
        s_x2d[1][p] = w00 * xb1[y0c * IMW + x0c] + w10 * xb1[y0c * IMW + x1c]
                    + w01 * xb1[y1c * IMW + x0c] + w11 * xb1[y1c * IMW + x1c];
    }
    __syncthreads();

    if (tid < 32) {
        float a = s_a[tid];
        float mx = a;
#pragma unroll
        for (int o = 16; o; o >>= 1) mx = fmaxf(mx, __shfl_xor_sync(0xffffffffu, mx, o));
        float e = __expf(a - mx);
        float sm = e;
#pragma unroll
        for (int o = 16; o; o >>= 1) sm += __shfl_xor_sync(0xffffffffu, sm, o);
        s_asm[tid] = (e / sm) * s_mask[tid];
    }
    __syncthreads();

    if (tid < 32) {
        float acc = 0.f;
#pragma unroll
        for (int pp = 0; pp < 32; pp++) acc += s_v[pp][tid] * s_asm[pp];
        attn_out[(size_t)nh * HD + tid] = acc;
        out_a[(size_t)nh * NP + tid]    = s_a[tid];
        out_m[(size_t)nh * NP + tid]    = s_mask[tid];
        out_x2d[(size_t)nh * 2 * NP + tid]      = s_x2d[0][tid];
        out_x2d[(size_t)nh * 2 * NP + 32 + tid] = s_x2d[1][tid];
    }

#pragma unroll
    for (int i = 0; i < 4; i++) {
        int idx = tid + i * 256;
        int d = idx >> 5, pp = idx & 31;
        out_v[(size_t)nh * (HD * NP) + idx] = s_v[pp][d];
    }
}

// ---------------- launch ----------------------------------------------------
extern "C" void kernel_launch(void* const* d_in, const int* in_sizes, int n_in,
                              void* d_out, int out_size) {
    const float* query    = (const float*)d_in[0];
    const float* obj_emb  = (const float*)d_in[1];
    const float* key_feat = (const float*)d_in[2];
    const float* value    = (const float*)d_in[3];
    const float* x2d      = (const float*)d_in[4];
    const float* maskin   = (const float*)d_in[5];
    const float* xy       = (const float*)d_in[6];
    const float* strides  = (const float*)d_in[7];
    const int*   imgind   = (const int*)d_in[8];
    const float* w_off    = (const float*)d_in[9];
    const float* b_off    = (const float*)d_in[10];
    const float* w_out    = (const float*)d_in[11];
    const float* b_out    = (const float*)d_in[12];
    const float* ln1_g    = (const float*)d_in[13];
    const float* ln1_b    = (const float*)d_in[14];
    const float* w1       = (const float*)d_in[15];
    const float* b1       = (const float*)d_in[16];
    const float* w2       = (const float*)d_in[17];
    const float* b2       = (const float*)d_in[18];
    const float* ln2_g    = (const float*)d_in[19];
    const float* ln2_b    = (const float*)d_in[20];
    float* out = (float*)d_out;

    float* out_out = out;                  // 2048*256
    float* out_v   = out + 524288;         // 2048*8*32*32
    float* out_a   = out + 17301504;       // 2048*8*1*32
    float* out_m   = out + 17825792;       // 2048*8*1*32
    float* out_x2d = out + 18350080;       // 2048*8*2*32

    float *p_off, *p_attn, *p_x1, *p_ffn, *p_part;
    cudaGetSymbolAddress((void**)&p_off,  g_offsets);
    cudaGetSymbolAddress((void**)&p_attn, g_attn);
    cudaGetSymbolAddress((void**)&p_x1,   g_x1);
    cudaGetSymbolAddress((void**)&p_ffn,  g_ffn);
    cudaGetSymbolAddress((void**)&p_part, g_part);

    // 1) layout transform of key/value for coalesced channel gathers
    transpose_kernel<<<dim3(HW / 32, NUM_IMG * NHD, 2), 256>>>(key_feat, value);

    // 2) sampling offsets GEMM: (2048x256)@(256x512)+b_off
    gemm64<<<dim3(8, 32, 1), 256>>>(obj_emb, w_off, b_off, p_off,
                                    NOBJ, NHD * NP * 2, EMBED, 0);

    // 3) bilinear sampling + attention (+ sample outputs)
    sample_kernel<<<NOBJ * NHD, 256>>>(query, x2d, maskin, xy, strides, imgind,
                                       out_v, out_a, out_m, out_x2d, p_attn);

    // 4) out-proj (split-K=2), then fused reduce + bias + residual + LN1
    gemm64<<<dim3(4, 32, 2), 256>>>(p_attn, w_out, nullptr, p_part,
                                    NOBJ, EMBED, EMBED, 3);
    reduce_ln_kernel<<<NOBJ, EMBED>>>(p_part, 2, b_out, obj_emb, ln1_g, ln1_b, p_x1);

    // 5) FFN1 (relu), FFN2 (split-K=4), fused reduce + bias + residual + LN2
    gemm64<<<dim3(16, 32, 1), 256>>>(p_x1, w1, b1, p_ffn,
                                     NOBJ, FFNW, EMBED, 2);
    gemm64<<<dim3(4, 32, 4), 256>>>(p_ffn, w2, nullptr, p_part,
                                    NOBJ, EMBED, FFNW, 3);
    reduce_ln_kernel<<<NOBJ, EMBED>>>(p_part, 4, b2, p_x1, ln2_g, ln2_b, out_out);
}

// round 16
// speedup vs baseline: 1.0076x; 1.0076x over previous
#include <cuda_runtime.h>

#define NOBJ  2048
#define NHD   8
#define NP    32
#define HD    32
#define EMBED 256
#define FFNW  1024
#define NUM_IMG 4
#define IMH   160
#define IMW   160
#define HW    25600     // 160*160
#define LN_EPS 1e-5f

// ---------------- scratch (device globals; no runtime alloc) ----------------
__device__ float g_keyT[(size_t)NUM_IMG * NHD * HW * HD];   // (img,h,pix,d) 100MB
__device__ float g_valT[(size_t)NUM_IMG * NHD * HW * HD];   // 100MB
__device__ float g_offsets[(size_t)NOBJ * NHD * NP * 2];
__device__ float g_attn[(size_t)NOBJ * EMBED];
__device__ float g_x1[(size_t)NOBJ * EMBED];
__device__ float g_ffn[(size_t)NOBJ * FFNW];
__device__ float g_part[(size_t)4 * NOBJ * EMBED];          // split-K partials (8MB)

// ---------------- transpose key/value: (img, c=h*32+d, y, x) -> (img,h, yx, d)
__global__ void transpose_kernel(const float* __restrict__ key_feat,
                                 const float* __restrict__ value) {
    __shared__ float sh[32][33];
    const float* in  = blockIdx.z ? value  : key_feat;
    float*       out = blockIdx.z ? g_valT : g_keyT;
    int ih  = blockIdx.y;              // img*8 + h
    int img = ih >> 3, h = ih & 7;
    int pix0 = blockIdx.x * 32;
    int t = threadIdx.x;
    size_t cbase = ((size_t)img * EMBED + h * HD) * HW;
#pragma unroll
    for (int pass = 0; pass < 4; pass++) {
        int c   = pass * 8 + (t >> 5);
        int pix = t & 31;
        sh[c][pix] = in[cbase + (size_t)c * HW + pix0 + pix];
    }
    __syncthreads();
    size_t obase = ((size_t)ih * HW + pix0) * HD;
#pragma unroll
    for (int pass = 0; pass < 4; pass++) {
        int pix = pass * 8 + (t >> 5);
        int c   = t & 31;
        out[obase + (size_t)pix * HD + c] = sh[c][pix];
    }
}

// ---------------- fp32 tiled GEMM, register double-buffered ----------------
// Tile 64x64, BK=16, 256 threads, 4x4 per thread.
// mode 0: C = A@B + bias
// mode 2: C = relu(A@B + bias)
// mode 3: split-K partial: g-part style, C + bz*M*N = A@B(chunk), raw
__global__ void gemm64(const float* __restrict__ A, const float* __restrict__ B,
                       const float* __restrict__ bias,
                       float* __restrict__ C, int M, int N, int K, int mode) {
    __shared__ float As[16][64];
    __shared__ float Bs[16][64];
    const int bm = blockIdx.y * 64, bn = blockIdx.x * 64;
    const int tid = threadIdx.x;
    const int tx = tid & 15, ty = tid >> 4;

    const int Kc    = K / gridDim.z;          // K-chunk for this block
    const int kbase = blockIdx.z * Kc;
    const int nk    = Kc >> 4;

    float acc[4][4];
#pragma unroll
    for (int i = 0; i < 4; i++)
#pragma unroll
        for (int j = 0; j < 4; j++) acc[i][j] = 0.f;

    const int arow = tid >> 2, aq = tid & 3;   // A: 64 rows x 4 float4
    const int brow = tid >> 4, bq = tid & 15;  // B: 16 rows x 16 float4

    const float* Aptr = A + (size_t)(bm + arow) * K + kbase + aq * 4;
    const float* Bptr = B + (size_t)(kbase + brow) * N + bn + bq * 4;

    // preload tile 0
    float4 a4 = *(const float4*)Aptr;
    float4 b4 = *(const float4*)Bptr;

    for (int kt = 0; kt < nk; kt++) {
        // store current tile to smem
        As[aq * 4 + 0][arow] = a4.x;
        As[aq * 4 + 1][arow] = a4.y;
        As[aq * 4 + 2][arow] = a4.z;
        As[aq * 4 + 3][arow] = a4.w;
        *(float4*)&Bs[brow][bq * 4] = b4;
        __syncthreads();

        // prefetch next tile while computing this one
        if (kt + 1 < nk) {
            a4 = *(const float4*)(Aptr + (kt + 1) * 16);
            b4 = *(const float4*)(Bptr + (size_t)(kt + 1) * 16 * N);
        }

#pragma unroll
        for (int kk = 0; kk < 16; kk++) {
            float4 av = *(const float4*)&As[kk][ty * 4];
            float4 bv = *(const float4*)&Bs[kk][tx * 4];
            float a[4] = {av.x, av.y, av.z, av.w};
            float b[4] = {bv.x, bv.y, bv.z, bv.w};
#pragma unroll
            for (int m = 0; m < 4; m++)
#pragma unroll
                for (int n = 0; n < 4; n++) acc[m][n] += a[m] * b[n];
        }
        __syncthreads();
    }

    float* Cb = (mode == 3) ? (C + (size_t)blockIdx.z * M * N) : C;
#pragma unroll
    for (int m = 0; m < 4; m++) {
        int r = bm + ty * 4 + m;
#pragma unroll
        for (int n = 0; n < 4; n++) {
            int c = bn + tx * 4 + n;
            float v = acc[m][n];
            if (mode != 3) v += bias[c];
            if (mode == 2) v = fmaxf(v, 0.f);
            Cb[(size_t)r * N + c] = v;
        }
    }
}

// ------- fused split-K reduce + bias + residual + layernorm (256 cols) ------
__device__ __forceinline__ float block_sum256(float v, float* red) {
#pragma unroll
    for (int o = 16; o; o >>= 1) v += __shfl_xor_sync(0xffffffffu, v, o);
    int warp = threadIdx.x >> 5;
    if ((threadIdx.x & 31) == 0) red[warp] = v;
    __syncthreads();
    float s = red[0] + red[1] + red[2] + red[3] + red[4] + red[5] + red[6] + red[7];
    __syncthreads();
    return s;
}

__global__ void reduce_ln_kernel(const float* __restrict__ part, int nsplit,
                                 const float* __restrict__ bias,
                                 const float* __restrict__ res,
                                 const float* __restrict__ g,
                                 const float* __restrict__ b,
                                 float* __restrict__ out) {
    __shared__ float red[8];
    int row = blockIdx.x, t = threadIdx.x;
    size_t off = (size_t)row * EMBED + t;
    float v = bias[t] + res[off];
#pragma unroll 4
    for (int s = 0; s < nsplit; s++)
        v += part[(size_t)s * NOBJ * EMBED + off];
    float mean = block_sum256(v, red) * (1.f / EMBED);
    float d = v - mean;
    float var = block_sum256(d * d, red) * (1.f / EMBED);
    out[off] = d * rsqrtf(var + LN_EPS) * g[t] + b[t];
}

// ---------------- sampling + attention: one block per (n, h) ----------------
__global__ void sample_kernel(const float* __restrict__ query,
                              const float* __restrict__ x2d,
                              const float* __restrict__ maskin,
                              const float* __restrict__ xy,
                              const float* __restrict__ strides,
                              const int*   __restrict__ imgind,
                              float* __restrict__ out_v, float* __restrict__ out_a,
                              float* __restrict__ out_m, float* __restrict__ out_x2d,
                              float* __restrict__ attn_out) {
    const int nh = blockIdx.x;
    const int n = nh >> 3, h = nh & 7;
    const int tid = threadIdx.x;
    const int p = tid >> 3, dg = tid & 7;

    __shared__ float s_v[NP][HD + 1];
    __shared__ float s_a[NP], s_asm[NP], s_mask[NP], s_x2d[2][NP];

    float st = strides[n];
    float ox = g_offsets[(size_t)n * 512 + (h * NP + p) * 2 + 0];
    float oy = g_offsets[(size_t)n * 512 + (h * NP + p) * 2 + 1];
    float lx = xy[n * 2 + 0] + ox * st;
    float ly = xy[n * 2 + 1] + oy * st;
    float gx = lx * (2.0f / (IMW * 4.0f)) - 1.0f;
    float gy = ly * (2.0f / (IMH * 4.0f)) - 1.0f;
    float ixf = ((gx + 1.0f) * IMW - 1.0f) * 0.5f;
    float iyf = ((gy + 1.0f) * IMH - 1.0f) * 0.5f;
    float x0f = floorf(ixf), y0f = floorf(iyf);
    float wx = ixf - x0f, wy = iyf - y0f;
    int x0 = (int)x0f, y0 = (int)y0f;
    int x1 = x0 + 1, y1 = y0 + 1;
    int x0c = min(max(x0, 0), IMW - 1), x1c = min(max(x1, 0), IMW - 1);
    int y0c = min(max(y0, 0), IMH - 1), y1c = min(max(y1, 0), IMH - 1);
    float w00 = (1.f - wx) * (1.f - wy), w10 = wx * (1.f - wy);
    float w01 = (1.f - wx) * wy,         w11 = wx * wy;

    int imi = imgind[n];
    size_t fb = ((size_t)(imi * NHD + h)) * HW;
    const float* kb = g_keyT + fb * HD;
    const float* vb = g_valT + fb * HD;
    size_t o00 = ((size_t)(y0c * IMW + x0c)) * HD + dg * 4;
    size_t o10 = ((size_t)(y0c * IMW + x1c)) * HD + dg * 4;
    size_t o01 = ((size_t)(y1c * IMW + x0c)) * HD + dg * 4;
    size_t o11 = ((size_t)(y1c * IMW + x1c)) * HD + dg * 4;

    float4 k00 = *(const float4*)(kb + o00);
    float4 k10 = *(const float4*)(kb + o10);
    float4 k01 = *(const float4*)(kb + o01);
    float4 k11 = *(const float4*)(kb + o11);
    float kv0 = w00 * k00.x + w10 * k10.x + w01 * k01.x + w11 * k11.x;
    float kv1 = w00 * k00.y + w10 * k10.y + w01 * k01.y + w11 * k11.y;
    float kv2 = w00 * k00.z + w10 * k10.z + w01 * k01.z + w11 * k11.z;
    float kv3 = w00 * k00.w + w10 * k10.w + w01 * k01.w + w11 * k11.w;

    float4 q4 = *(const float4*)(query + (size_t)nh * HD + dg * 4);
    float part = q4.x * kv0 + q4.y * kv1 + q4.z * kv2 + q4.w * kv3;

    float4 v00 = *(const float4*)(vb + o00);
    float4 v10 = *(const float4*)(vb + o10);
    float4 v01 = *(const float4*)(vb + o01);
    float4 v11 = *(const float4*)(vb + o11);
    s_v[p][dg * 4 + 0] = w00 * v00.x + w10 * v10.x + w01 * v01.x + w11 * v11.x;
    s_v[p][dg * 4 + 1] = w00 * v00.y + w10 * v10.y + w01 * v01.y + w11 * v11.y;
    s_v[p][dg * 4 + 2] = w00 * v00.z + w10 * v10.z + w01 * v01.z + w11 * v11.z;
    s_v[p][dg * 4 + 3] = w00 * v00.w + w10 * v10.w + w01 * v01.w + w11 * v11.w;

    part += __shfl_xor_sync(0xffffffffu, part, 1);
    part += __shfl_xor_sync(0xffffffffu, part, 2);
    part += __shfl_xor_sync(0xffffffffu, part, 4);

    if (dg == 0) {
        s_a[p] = part * 0.17677669529663687f;   // 1/sqrt(HD)
        const float* mb = maskin + (size_t)imi * HW;
        float m = 0.f;
        if (x0 >= 0 && x0 < IMW && y0 >= 0 && y0 < IMH) m += w00 * mb[y0c * IMW + x0c];
        if (x1 >= 0 && x1 < IMW && y0 >= 0 && y0 < IMH) m += w10 * mb[y0c * IMW + x1c];
        if (x0 >= 0 && x0 < IMW && y1 >= 0 && y1 < IMH) m += w01 * mb[y1c * IMW + x0c];
        if (x1 >= 0 && x1 < IMW && y1 >= 0 && y1 < IMH) m += w11 * mb[y1c * IMW + x1c];
        s_mask[p] = m;
        const float* xb0 = x2d + (size_t)imi * 2 * HW;
        const float* xb1 = xb0 + HW;
        s_x2d[0][p] = w00 * xb0[y0c * IMW + x0c] + w10 * xb0[y0c * IMW + x1c]
                    + w01 * xb0[y1c * IMW + x0c] + w11 * xb0[y1c * IMW + x1c];
        s_x2d[1][p] = w00 * xb1[y0c * IMW + x0c] + w10 * xb1[y0c * IMW + x1c]
                    + w01 * xb1[y1c * IMW + x0c] + w11 * xb1[y1c * IMW + x1c];
    }
    __syncthreads();

    if (tid < 32) {
        float a = s_a[tid];
        float mx = a;
#pragma unroll
        for (int o = 16; o; o >>= 1) mx = fmaxf(mx, __shfl_xor_sync(0xffffffffu, mx, o));
        float e = __expf(a - mx);
        float sm = e;
#pragma unroll
        for (int o = 16; o; o >>= 1) sm += __shfl_xor_sync(0xffffffffu, sm, o);
        s_asm[tid] = (e / sm) * s_mask[tid];
    }
    __syncthreads();

    if (tid < 32) {
        float acc = 0.f;
#pragma unroll
        for (int pp = 0; pp < 32; pp++) acc += s_v[pp][tid] * s_asm[pp];
        attn_out[(size_t)nh * HD + tid] = acc;
        out_a[(size_t)nh * NP + tid]    = s_a[tid];
        out_m[(size_t)nh * NP + tid]    = s_mask[tid];
        out_x2d[(size_t)nh * 2 * NP + tid]      = s_x2d[0][tid];
        out_x2d[(size_t)nh * 2 * NP + 32 + tid] = s_x2d[1][tid];
    }

#pragma unroll
    for (int i = 0; i < 4; i++) {
        int idx = tid + i * 256;
        int d = idx >> 5, pp = idx & 31;
        out_v[(size_t)nh * (HD * NP) + idx] = s_v[pp][d];
    }
}

// ---------------- launch ----------------------------------------------------
extern "C" void kernel_launch(void* const* d_in, const int* in_sizes, int n_in,
                              void* d_out, int out_size) {
    const float* query    = (const float*)d_in[0];
    const float* obj_emb  = (const float*)d_in[1];
    const float* key_feat = (const float*)d_in[2];
    const float* value    = (const float*)d_in[3];
    const float* x2d      = (const float*)d_in[4];
    const float* maskin   = (const float*)d_in[5];
    const float* xy       = (const float*)d_in[6];
    const float* strides  = (const float*)d_in[7];
    const int*   imgind   = (const int*)d_in[8];
    const float* w_off    = (const float*)d_in[9];
    const float* b_off    = (const float*)d_in[10];
    const float* w_out    = (const float*)d_in[11];
    const float* b_out    = (const float*)d_in[12];
    const float* ln1_g    = (const float*)d_in[13];
    const float* ln1_b    = (const float*)d_in[14];
    const float* w1       = (const float*)d_in[15];
    const float* b1       = (const float*)d_in[16];
    const float* w2       = (const float*)d_in[17];
    const float* b2       = (const float*)d_in[18];
    const float* ln2_g    = (const float*)d_in[19];
    const float* ln2_b    = (const float*)d_in[20];
    float* out = (float*)d_out;

    float* out_out = out;                  // 2048*256
    float* out_v   = out + 524288;         // 2048*8*32*32
    float* out_a   = out + 17301504;       // 2048*8*1*32
    float* out_m   = out + 17825792;       // 2048*8*1*32
    float* out_x2d = out + 18350080;       // 2048*8*2*32

    float *p_off, *p_attn, *p_x1, *p_ffn, *p_part;
    cudaGetSymbolAddress((void**)&p_off,  g_offsets);
    cudaGetSymbolAddress((void**)&p_attn, g_attn);
    cudaGetSymbolAddress((void**)&p_x1,   g_x1);
    cudaGetSymbolAddress((void**)&p_ffn,  g_ffn);
    cudaGetSymbolAddress((void**)&p_part, g_part);

    // 1) layout transform of key/value for coalesced channel gathers
    transpose_kernel<<<dim3(HW / 32, NUM_IMG * NHD, 2), 256>>>(key_feat, value);

    // 2) sampling offsets GEMM: (2048x256)@(256x512)+b_off
    gemm64<<<dim3(8, 32, 1), 256>>>(obj_emb, w_off, b_off, p_off,
                                    NOBJ, NHD * NP * 2, EMBED, 0);

    // 3) bilinear sampling + attention (+ sample outputs)
    sample_kernel<<<NOBJ * NHD, 256>>>(query, x2d, maskin, xy, strides, imgind,
                                       out_v, out_a, out_m, out_x2d, p_attn);

    // 4) out-proj (split-K=2), then fused reduce + bias + residual + LN1
    gemm64<<<dim3(4, 32, 2), 256>>>(p_attn, w_out, nullptr, p_part,
                                    NOBJ, EMBED, EMBED, 3);
    reduce_ln_kernel<<<NOBJ, EMBED>>>(p_part, 2, b_out, obj_emb, ln1_g, ln1_b, p_x1);

    // 5) FFN1 (relu), FFN2 (split-K=4), fused reduce + bias + residual + LN2
    gemm64<<<dim3(16, 32, 1), 256>>>(p_x1, w1, b1, p_ffn,
                                     NOBJ, FFNW, EMBED, 2);
    gemm64<<<dim3(4, 32, 4), 256>>>(p_ffn, w2, nullptr, p_part,
                                    NOBJ, EMBED, FFNW, 3);
    reduce_ln_kernel<<<NOBJ, EMBED>>>(p_part, 4, b2, p_x1, ln2_g, ln2_b, out_out);
}